// round 1
// baseline (speedup 1.0000x reference)
#include <cuda_runtime.h>

#define NN 50000
#define EE 400000
#define EPSBN 1e-5f

// ---------------- scratch (device globals: allocation-free) ----------------
__device__ float g_s[(size_t)NN * 128];     // GEMM output ("support")
__device__ float g_h[(size_t)NN * 128];     // scatter accumulation (gcn output)
__device__ float g_x[(size_t)NN * 128];     // current x
__device__ float g_inp[(size_t)NN * 128];   // residual input
__device__ float g_t[(size_t)NN * 128];     // mixed input to GEMM
__device__ float g_alpha[NN];
__device__ float g_stats[256];              // [0:128) sum, [128:256) sumsq

// ---------------- GEMM: out(g_s)[M, ldo] = A[M,128] @ W[128,Nout] ----------
// A == nullptr means "read g_t". Batch (blockIdx.z) offsets A, W and the
// output column (colOffPerBatch) so the two init GCNs write concat layout.
__global__ __launch_bounds__(256) void gemm_k(
    const float* __restrict__ A, long aBatch,
    const float* __restrict__ W, long wBatch,
    int colOffPerBatch, int ldo, int M, int Nout)
{
    __shared__ float As[64][65];   // padded: conflict-free scalar column reads
    __shared__ float Ws[64][64];
    if (A == nullptr) A = g_t;
    int b = blockIdx.z;
    A += (size_t)b * aBatch;
    W += (size_t)b * wBatch;
    int rowBase = blockIdx.y * 64;
    int colBase = blockIdx.x * 64;
    int tid = threadIdx.x;
    int tx = tid & 15, ty = tid >> 4;

    float acc[4][4] = {};
    for (int k0 = 0; k0 < 128; k0 += 64) {
        // load A tile 64x64 (float4 global reads, scalar smem stores for pad)
        #pragma unroll
        for (int i = tid; i < 1024; i += 256) {
            int r = i >> 4, c4 = i & 15;
            int gr = rowBase + r;
            float4 v = make_float4(0.f, 0.f, 0.f, 0.f);
            if (gr < M) v = *(const float4*)(A + (size_t)gr * 128 + k0 + c4 * 4);
            As[r][c4 * 4 + 0] = v.x; As[r][c4 * 4 + 1] = v.y;
            As[r][c4 * 4 + 2] = v.z; As[r][c4 * 4 + 3] = v.w;
        }
        // load W tile 64x64
        #pragma unroll
        for (int i = tid; i < 1024; i += 256) {
            int kk = i >> 4, c4 = i & 15;
            float4 v = *(const float4*)(W + (size_t)(k0 + kk) * Nout + colBase + c4 * 4);
            *(float4*)&Ws[kk][c4 * 4] = v;
        }
        __syncthreads();
        #pragma unroll
        for (int k = 0; k < 64; k++) {
            float4 w4 = *(float4*)&Ws[k][tx * 4];
            float a[4];
            #pragma unroll
            for (int r = 0; r < 4; r++) a[r] = As[ty * 4 + r][k];
            #pragma unroll
            for (int r = 0; r < 4; r++) {
                acc[r][0] += a[r] * w4.x;
                acc[r][1] += a[r] * w4.y;
                acc[r][2] += a[r] * w4.z;
                acc[r][3] += a[r] * w4.w;
            }
        }
        __syncthreads();
    }
    int colOff = colBase + b * colOffPerBatch;
    #pragma unroll
    for (int r = 0; r < 4; r++) {
        int gr = rowBase + ty * 4 + r;
        if (gr < M) {
            float4 o = make_float4(acc[r][0], acc[r][1], acc[r][2], acc[r][3]);
            *(float4*)(g_s + (size_t)gr * ldo + colOff + tx * 4) = o;
        }
    }
}

// ---------------- init h to broadcast bias; zero BN stats ------------------
__global__ __launch_bounds__(256) void init_h_k(const float* __restrict__ bias,
                                                int mask4, long total4)
{
    long i = (long)blockIdx.x * blockDim.x + threadIdx.x;
    if (blockIdx.x == 0 && threadIdx.x < 256) g_stats[threadIdx.x] = 0.f;
    if (i < total4) {
        float4 bv = ((const float4*)bias)[i & mask4];
        ((float4*)g_h)[i] = bv;
    }
}

// ---------------- edge scatter: h[dst] += w * s[src] -----------------------
// 128-wide: one warp per edge, one float4 per lane (coalesced gather row).
__global__ __launch_bounds__(256) void scatter128_k(const int* __restrict__ src,
                                                    const int* __restrict__ dst,
                                                    const float* __restrict__ ew)
{
    int warp = (blockIdx.x * blockDim.x + threadIdx.x) >> 5;
    if (warp >= EE) return;
    int lane = threadIdx.x & 31;
    int u = __ldg(&src[warp]);
    int v = __ldg(&dst[warp]);
    float w = __ldg(&ew[warp]);
    float4 val = ((const float4*)(g_s + (size_t)u * 128))[lane];
    float* p = g_h + (size_t)v * 128 + lane * 4;
    atomicAdd(p + 0, w * val.x);
    atomicAdd(p + 1, w * val.y);
    atomicAdd(p + 2, w * val.z);
    atomicAdd(p + 3, w * val.w);
}

// 64-wide: half-warp per edge
__global__ __launch_bounds__(256) void scatter64_k(const int* __restrict__ src,
                                                   const int* __restrict__ dst,
                                                   const float* __restrict__ ew)
{
    int idx = blockIdx.x * blockDim.x + threadIdx.x;
    int e = idx >> 4;
    if (e >= EE) return;
    int lane = idx & 15;
    int u = __ldg(&src[e]);
    int v = __ldg(&dst[e]);
    float w = __ldg(&ew[e]);
    float4 val = ((const float4*)(g_s + (size_t)u * 64))[lane];
    float* p = g_h + (size_t)v * 64 + lane * 4;
    atomicAdd(p + 0, w * val.x);
    atomicAdd(p + 1, w * val.y);
    atomicAdd(p + 2, w * val.z);
    atomicAdd(p + 3, w * val.w);
}

// ---------------- BN stats: per-column sum & sumsq over N rows -------------
__global__ __launch_bounds__(256) void stats_k()
{
    int tid = threadIdx.x;
    int c = tid & 127;
    int rh = tid >> 7;      // 0/1
    float sum = 0.f, sq = 0.f;
    for (int r = blockIdx.x * 2 + rh; r < NN; r += gridDim.x * 2) {
        float v = g_h[(size_t)r * 128 + c];
        sum += v;
        sq += v * v;
    }
    __shared__ float sh[256];
    sh[tid] = sum; __syncthreads();
    float s2 = (rh == 0) ? sum + sh[tid + 128] : 0.f;
    __syncthreads();
    sh[tid] = sq; __syncthreads();
    if (rh == 0) {
        float q2 = sq + sh[tid + 128];
        atomicAdd(&g_stats[c], s2);
        atomicAdd(&g_stats[128 + c], q2);
    }
}

// ---------------- normalize + relu -> g_x (and g_inp if flag) --------------
__global__ __launch_bounds__(256) void norm_relu_k(int writeInp)
{
    __shared__ float sm[128], sv[128];
    int tid = threadIdx.x;
    if (tid < 128) {
        float mu = g_stats[tid] * (1.f / NN);
        float var = g_stats[128 + tid] * (1.f / NN) - mu * mu;
        sm[tid] = mu;
        sv[tid] = rsqrtf(var + EPSBN);
    }
    __syncthreads();
    long i = (long)blockIdx.x * blockDim.x + tid;
    if (i >= (long)NN * 32) return;
    int c = (i & 31) * 4;
    float4 v = ((const float4*)g_h)[i];
    float4 o;
    o.x = fmaxf((v.x - sm[c + 0]) * sv[c + 0], 0.f);
    o.y = fmaxf((v.y - sm[c + 1]) * sv[c + 1], 0.f);
    o.z = fmaxf((v.z - sm[c + 2]) * sv[c + 2], 0.f);
    o.w = fmaxf((v.w - sm[c + 3]) * sv[c + 3], 0.f);
    ((float4*)g_x)[i] = o;
    if (writeInp) ((float4*)g_inp)[i] = o;
}

// ---------------- alpha = sigmoid([inp,x] @ linW + b); t = mix -------------
__global__ __launch_bounds__(256) void alpha_mix_k(const float* __restrict__ linW,
                                                   const float* __restrict__ linb)
{
    int warp = (blockIdx.x * blockDim.x + threadIdx.x) >> 5;
    if (warp >= NN) return;
    int lane = threadIdx.x & 31;
    float4 xi = ((const float4*)(g_x + (size_t)warp * 128))[lane];
    float4 ii = ((const float4*)(g_inp + (size_t)warp * 128))[lane];
    float4 w1 = ((const float4*)linW)[lane];          // rows 0..127 (inp)
    float4 w2 = ((const float4*)(linW + 128))[lane];  // rows 128..255 (x)
    float d = ii.x * w1.x + ii.y * w1.y + ii.z * w1.z + ii.w * w1.w
            + xi.x * w2.x + xi.y * w2.y + xi.z * w2.z + xi.w * w2.w;
    #pragma unroll
    for (int o = 16; o; o >>= 1) d += __shfl_xor_sync(0xFFFFFFFFu, d, o);
    float a = 1.f / (1.f + expf(-(d + linb[0])));
    float4 tv;
    tv.x = a * xi.x + (1.f - a) * ii.x;
    tv.y = a * xi.y + (1.f - a) * ii.y;
    tv.z = a * xi.z + (1.f - a) * ii.z;
    tv.w = a * xi.w + (1.f - a) * ii.w;
    ((float4*)(g_t + (size_t)warp * 128))[lane] = tv;
    if (lane == 0) g_alpha[warp] = a;
}

// ---------------- final mix with stored (reused) alpha ---------------------
__global__ __launch_bounds__(256) void final_mix_k()
{
    long i = (long)blockIdx.x * blockDim.x + threadIdx.x;
    if (i >= (long)NN * 32) return;
    int n = (int)(i >> 5);
    float a = g_alpha[n];
    float4 xi = ((const float4*)g_x)[i];
    float4 ii = ((const float4*)g_inp)[i];
    float4 tv;
    tv.x = a * xi.x + (1.f - a) * ii.x;
    tv.y = a * xi.y + (1.f - a) * ii.y;
    tv.z = a * xi.z + (1.f - a) * ii.z;
    tv.w = a * xi.w + (1.f - a) * ii.w;
    ((float4*)g_t)[i] = tv;
}

// ---------------- log_softmax over 64 cols (warp per row) ------------------
__global__ __launch_bounds__(256) void logsoftmax_k(float* __restrict__ out)
{
    int warp = (blockIdx.x * blockDim.x + threadIdx.x) >> 5;
    if (warp >= NN) return;
    int lane = threadIdx.x & 31;
    float2 v = ((const float2*)(g_h + (size_t)warp * 64))[lane];
    float m = fmaxf(v.x, v.y);
    #pragma unroll
    for (int o = 16; o; o >>= 1) m = fmaxf(m, __shfl_xor_sync(0xFFFFFFFFu, m, o));
    float s = expf(v.x - m) + expf(v.y - m);
    #pragma unroll
    for (int o = 16; o; o >>= 1) s += __shfl_xor_sync(0xFFFFFFFFu, s, o);
    float l = m + logf(s);
    float2 r = make_float2(v.x - l, v.y - l);
    ((float2*)(out + (size_t)warp * 64))[lane] = r;
}

// ---------------- launch sequence ------------------------------------------
extern "C" void kernel_launch(void* const* d_in, const int* in_sizes, int n_in,
                              void* d_out, int out_size)
{
    const float* x_list = (const float*)d_in[0];   // [2, N, 128]
    const int*   esrc   = (const int*)d_in[1];     // [E]
    const int*   edst   = (const int*)d_in[2];     // [E]
    const float* ew     = (const float*)d_in[3];   // [E]
    const float* W_init = (const float*)d_in[4];   // [2,128,64]
    const float* b_init = (const float*)d_in[5];   // [2,64] == concat [128]
    const float* W_mid  = (const float*)d_in[6];   // [2,128,128]
    const float* b_mid  = (const float*)d_in[7];   // [2,128]
    const float* W_last = (const float*)d_in[8];   // [128,64]
    const float* b_last = (const float*)d_in[9];   // [64]
    const float* linW   = (const float*)d_in[10];  // [256]
    const float* linb   = (const float*)d_in[11];  // [1]
    float* out = (float*)d_out;

    const int rowsG = (NN + 63) / 64;            // 782
    const int blkElem128 = (NN * 32 + 255) / 256; // float4 passes over [N,128]
    const int blkScatter128 = (EE * 32) / 256;    // 50000
    const int blkScatter64  = (EE * 16) / 256;    // 25000
    const int blkWarpRow = (NN * 32 + 255) / 256; // 6250

    // init GCNs (fused concat): s[:,0:64]=x0@W0, s[:,64:128]=x1@W1
    gemm_k<<<dim3(1, rowsG, 2), 256>>>(x_list, (long)NN * 128,
                                       W_init, (long)128 * 64, 64, 128, NN, 64);
    init_h_k<<<blkElem128, 256>>>(b_init, 31, (long)NN * 32);
    scatter128_k<<<blkScatter128, 256>>>(esrc, edst, ew);
    stats_k<<<512, 256>>>();
    norm_relu_k<<<blkElem128, 256>>>(1);   // x and inp

    for (int i = 0; i < 2; i++) {
        alpha_mix_k<<<blkWarpRow, 256>>>(linW, linb);
        gemm_k<<<dim3(2, rowsG, 1), 256>>>(nullptr, 0,
                                           W_mid + (size_t)i * 128 * 128, 0,
                                           0, 128, NN, 128);
        init_h_k<<<blkElem128, 256>>>(b_mid + (size_t)i * 128, 31, (long)NN * 32);
        scatter128_k<<<blkScatter128, 256>>>(esrc, edst, ew);
        stats_k<<<512, 256>>>();
        norm_relu_k<<<blkElem128, 256>>>(0);  // x only
    }

    final_mix_k<<<blkElem128, 256>>>();
    gemm_k<<<dim3(1, rowsG, 1), 256>>>(nullptr, 0, W_last, 0, 0, 64, NN, 64);
    init_h_k<<<(NN * 16 + 255) / 256, 256>>>(b_last, 15, (long)NN * 16);
    scatter64_k<<<blkScatter64, 256>>>(esrc, edst, ew);
    logsoftmax_k<<<blkWarpRow, 256>>>(out);
}

// round 2
// speedup vs baseline: 1.5565x; 1.5565x over previous
#include <cuda_runtime.h>

#define NN 50000
#define EE 400000
#define EPSBN 1e-5f

// ---------------- scratch (device globals: allocation-free) ----------------
__device__ float g_s[(size_t)NN * 128];     // GEMM output ("support")
__device__ float g_h[(size_t)NN * 128];     // scatter accumulation (128-wide)
__device__ float g_h64[(size_t)NN * 64];    // scatter accumulation (64-wide, last)
__device__ float g_inp[(size_t)NN * 128];   // residual input
__device__ float g_t[(size_t)NN * 128];     // mixed input to GEMM
__device__ float g_alpha[NN];
__device__ __align__(16) float g_stats[256]; // [0:128) sum, [128:256) sumsq

// ---------------- GEMM: g_s[M, ldo] = A[M,128] @ W[128,Nout] ---------------
// A == nullptr means "read g_t". blockIdx.z batches A/W and offsets output
// columns (concat layout for the two init GCNs). Block (0,0,0) zeroes stats.
__global__ __launch_bounds__(256) void gemm_k(
    const float* __restrict__ A, long aBatch,
    const float* __restrict__ W, long wBatch,
    int colOffPerBatch, int ldo, int M, int Nout)
{
    __shared__ float As[64][65];
    __shared__ float Ws[64][64];
    int tid = threadIdx.x;
    if (blockIdx.x == 0 && blockIdx.y == 0 && blockIdx.z == 0 && tid < 256)
        g_stats[tid] = 0.f;
    if (A == nullptr) A = g_t;
    int b = blockIdx.z;
    A += (size_t)b * aBatch;
    W += (size_t)b * wBatch;
    int rowBase = blockIdx.y * 64;
    int colBase = blockIdx.x * 64;
    int tx = tid & 15, ty = tid >> 4;

    float acc[4][4] = {};
    for (int k0 = 0; k0 < 128; k0 += 64) {
        #pragma unroll
        for (int i = tid; i < 1024; i += 256) {
            int r = i >> 4, c4 = i & 15;
            int gr = rowBase + r;
            float4 v = make_float4(0.f, 0.f, 0.f, 0.f);
            if (gr < M) v = *(const float4*)(A + (size_t)gr * 128 + k0 + c4 * 4);
            As[r][c4 * 4 + 0] = v.x; As[r][c4 * 4 + 1] = v.y;
            As[r][c4 * 4 + 2] = v.z; As[r][c4 * 4 + 3] = v.w;
        }
        #pragma unroll
        for (int i = tid; i < 1024; i += 256) {
            int kk = i >> 4, c4 = i & 15;
            float4 v = *(const float4*)(W + (size_t)(k0 + kk) * Nout + colBase + c4 * 4);
            *(float4*)&Ws[kk][c4 * 4] = v;
        }
        __syncthreads();
        #pragma unroll
        for (int k = 0; k < 64; k++) {
            float4 w4 = *(float4*)&Ws[k][tx * 4];
            float a[4];
            #pragma unroll
            for (int r = 0; r < 4; r++) a[r] = As[ty * 4 + r][k];
            #pragma unroll
            for (int r = 0; r < 4; r++) {
                acc[r][0] += a[r] * w4.x;
                acc[r][1] += a[r] * w4.y;
                acc[r][2] += a[r] * w4.z;
                acc[r][3] += a[r] * w4.w;
            }
        }
        __syncthreads();
    }
    int colOff = colBase + b * colOffPerBatch;
    #pragma unroll
    for (int r = 0; r < 4; r++) {
        int gr = rowBase + ty * 4 + r;
        if (gr < M) {
            float4 o = make_float4(acc[r][0], acc[r][1], acc[r][2], acc[r][3]);
            *(float4*)(g_s + (size_t)gr * ldo + colOff + tx * 4) = o;
        }
    }
}

// ---------------- init h to broadcast bias (first layer only) --------------
__global__ __launch_bounds__(256) void init_h_k(const float* __restrict__ bias)
{
    long i = (long)blockIdx.x * blockDim.x + threadIdx.x;
    if (i < (long)NN * 32) {
        float4 bv = ((const float4*)bias)[i & 31];
        ((float4*)g_h)[i] = bv;
    }
}

// ---------------- edge scatter: h[dst] += w * s[src], v4 RED ---------------
__device__ __forceinline__ void red_v4(float* p, float4 v) {
    asm volatile("red.global.add.v4.f32 [%0], {%1, %2, %3, %4};"
                 :: "l"(p), "f"(v.x), "f"(v.y), "f"(v.z), "f"(v.w)
                 : "memory");
}

__global__ __launch_bounds__(256) void scatter128_k(const int* __restrict__ src,
                                                    const int* __restrict__ dst,
                                                    const float* __restrict__ ew)
{
    int warp = (blockIdx.x * blockDim.x + threadIdx.x) >> 5;
    if (warp >= EE) return;
    int lane = threadIdx.x & 31;
    int u = __ldg(&src[warp]);
    int v = __ldg(&dst[warp]);
    float w = __ldg(&ew[warp]);
    float4 val = ((const float4*)(g_s + (size_t)u * 128))[lane];
    val.x *= w; val.y *= w; val.z *= w; val.w *= w;
    red_v4(g_h + (size_t)v * 128 + lane * 4, val);
}

__global__ __launch_bounds__(256) void scatter64_k(const int* __restrict__ src,
                                                   const int* __restrict__ dst,
                                                   const float* __restrict__ ew)
{
    int idx = blockIdx.x * blockDim.x + threadIdx.x;
    int e = idx >> 4;
    if (e >= EE) return;
    int lane = idx & 15;
    int u = __ldg(&src[e]);
    int v = __ldg(&dst[e]);
    float w = __ldg(&ew[e]);
    float4 val = ((const float4*)(g_s + (size_t)u * 64))[lane];
    val.x *= w; val.y *= w; val.z *= w; val.w *= w;
    red_v4(g_h64 + (size_t)v * 64 + lane * 4, val);
}

// ---------------- BN stats: per-column sum & sumsq over N rows -------------
__global__ __launch_bounds__(256) void stats_k()
{
    int tid = threadIdx.x;
    int cg = tid & 31;   // column group (4 cols)
    int ro = tid >> 5;   // 0..7
    float4 s = make_float4(0.f, 0.f, 0.f, 0.f);
    float4 q = make_float4(0.f, 0.f, 0.f, 0.f);
    int stride = gridDim.x * 8;
    #pragma unroll 4
    for (int r = blockIdx.x * 8 + ro; r < NN; r += stride) {
        float4 v = ((const float4*)(g_h + (size_t)r * 128))[cg];
        s.x += v.x; s.y += v.y; s.z += v.z; s.w += v.w;
        q.x += v.x * v.x; q.y += v.y * v.y; q.z += v.z * v.z; q.w += v.w * v.w;
    }
    __shared__ float4 shs[256], shq[256];
    shs[tid] = s; shq[tid] = q;
    __syncthreads();
    #pragma unroll
    for (int off = 128; off >= 32; off >>= 1) {
        if (tid < off) {
            float4 a = shs[tid], b = shs[tid + off];
            a.x += b.x; a.y += b.y; a.z += b.z; a.w += b.w;
            shs[tid] = a;
            float4 c = shq[tid], d = shq[tid + off];
            c.x += d.x; c.y += d.y; c.z += d.z; c.w += d.w;
            shq[tid] = c;
        }
        __syncthreads();
    }
    if (tid < 32) {
        float4 a = shs[tid], c = shq[tid];
        int col = tid * 4;
        atomicAdd(&g_stats[col + 0], a.x);
        atomicAdd(&g_stats[col + 1], a.y);
        atomicAdd(&g_stats[col + 2], a.z);
        atomicAdd(&g_stats[col + 3], a.w);
        atomicAdd(&g_stats[128 + col + 0], c.x);
        atomicAdd(&g_stats[128 + col + 1], c.y);
        atomicAdd(&g_stats[128 + col + 2], c.z);
        atomicAdd(&g_stats[128 + col + 3], c.w);
    }
}

// ---------------- fused BN helpers -----------------------------------------
__device__ __forceinline__ float4 bn_relu4(float4 h, int cg) {
    float4 su = ((const float4*)g_stats)[cg];
    float4 sq = ((const float4*)g_stats)[32 + cg];
    const float invN = 1.f / NN;
    float4 o;
    float mu, var;
    mu = su.x * invN; var = sq.x * invN - mu * mu;
    o.x = fmaxf((h.x - mu) * rsqrtf(var + EPSBN), 0.f);
    mu = su.y * invN; var = sq.y * invN - mu * mu;
    o.y = fmaxf((h.y - mu) * rsqrtf(var + EPSBN), 0.f);
    mu = su.z * invN; var = sq.z * invN - mu * mu;
    o.z = fmaxf((h.z - mu) * rsqrtf(var + EPSBN), 0.f);
    mu = su.w * invN; var = sq.w * invN - mu * mu;
    o.w = fmaxf((h.w - mu) * rsqrtf(var + EPSBN), 0.f);
    return o;
}

// After first scatter+stats: x = relu(bn(h)); inp = t = x (first mix is
// identity since inp == x). Overwrite h with next layer's bias.
__global__ __launch_bounds__(256) void fuse_first_k(const float* __restrict__ bNext)
{
    int warp = (blockIdx.x * blockDim.x + threadIdx.x) >> 5;
    if (warp >= NN) return;
    int lane = threadIdx.x & 31;
    size_t off = (size_t)warp * 32 + lane;
    float4 x = bn_relu4(((const float4*)g_h)[off], lane);
    ((float4*)g_inp)[off] = x;
    ((float4*)g_t)[off] = x;
    ((float4*)g_h)[off] = ((const float4*)bNext)[lane];
}

// Mid fusion: x = relu(bn(h)); alpha = sigmoid([inp,x]@linW + b);
// t = alpha*x + (1-alpha)*inp; store alpha; h = next bias.
__global__ __launch_bounds__(256) void fuse_mid_k(const float* __restrict__ linW,
                                                  const float* __restrict__ linb,
                                                  const float* __restrict__ bNext)
{
    int warp = (blockIdx.x * blockDim.x + threadIdx.x) >> 5;
    if (warp >= NN) return;
    int lane = threadIdx.x & 31;
    size_t off = (size_t)warp * 32 + lane;
    float4 x = bn_relu4(((const float4*)g_h)[off], lane);
    float4 ii = ((const float4*)g_inp)[off];
    float4 w1 = ((const float4*)linW)[lane];        // rows 0..127 -> inp
    float4 w2 = ((const float4*)(linW + 128))[lane];// rows 128..255 -> x
    float d = ii.x * w1.x + ii.y * w1.y + ii.z * w1.z + ii.w * w1.w
            + x.x * w2.x + x.y * w2.y + x.z * w2.z + x.w * w2.w;
    #pragma unroll
    for (int o = 16; o; o >>= 1) d += __shfl_xor_sync(0xFFFFFFFFu, d, o);
    float a = 1.f / (1.f + expf(-(d + linb[0])));
    float4 tv;
    tv.x = a * x.x + (1.f - a) * ii.x;
    tv.y = a * x.y + (1.f - a) * ii.y;
    tv.z = a * x.z + (1.f - a) * ii.z;
    tv.w = a * x.w + (1.f - a) * ii.w;
    ((float4*)g_t)[off] = tv;
    if (lane == 0) g_alpha[warp] = a;
    ((float4*)g_h)[off] = ((const float4*)bNext)[lane];
}

// Final fusion: x = relu(bn(h)); t = alpha*x + (1-alpha)*inp (alpha reused);
// init 64-wide h64 = b_last.
__global__ __launch_bounds__(256) void fuse_final_k(const float* __restrict__ bLast)
{
    int warp = (blockIdx.x * blockDim.x + threadIdx.x) >> 5;
    if (warp >= NN) return;
    int lane = threadIdx.x & 31;
    size_t off = (size_t)warp * 32 + lane;
    float4 x = bn_relu4(((const float4*)g_h)[off], lane);
    float4 ii = ((const float4*)g_inp)[off];
    float a = g_alpha[warp];
    float4 tv;
    tv.x = a * x.x + (1.f - a) * ii.x;
    tv.y = a * x.y + (1.f - a) * ii.y;
    tv.z = a * x.z + (1.f - a) * ii.z;
    tv.w = a * x.w + (1.f - a) * ii.w;
    ((float4*)g_t)[off] = tv;
    if (lane < 16)
        ((float4*)(g_h64 + (size_t)warp * 64))[lane] = ((const float4*)bLast)[lane];
}

// ---------------- log_softmax over 64 cols (warp per row) ------------------
__global__ __launch_bounds__(256) void logsoftmax_k(float* __restrict__ out)
{
    int warp = (blockIdx.x * blockDim.x + threadIdx.x) >> 5;
    if (warp >= NN) return;
    int lane = threadIdx.x & 31;
    float2 v = ((const float2*)(g_h64 + (size_t)warp * 64))[lane];
    float m = fmaxf(v.x, v.y);
    #pragma unroll
    for (int o = 16; o; o >>= 1) m = fmaxf(m, __shfl_xor_sync(0xFFFFFFFFu, m, o));
    float s = expf(v.x - m) + expf(v.y - m);
    #pragma unroll
    for (int o = 16; o; o >>= 1) s += __shfl_xor_sync(0xFFFFFFFFu, s, o);
    float l = m + logf(s);
    float2 r = make_float2(v.x - l, v.y - l);
    ((float2*)(out + (size_t)warp * 64))[lane] = r;
}

// ---------------- launch sequence ------------------------------------------
extern "C" void kernel_launch(void* const* d_in, const int* in_sizes, int n_in,
                              void* d_out, int out_size)
{
    const float* x_list = (const float*)d_in[0];   // [2, N, 128]
    const int*   esrc   = (const int*)d_in[1];     // [E]
    const int*   edst   = (const int*)d_in[2];     // [E]
    const float* ew     = (const float*)d_in[3];   // [E]
    const float* W_init = (const float*)d_in[4];   // [2,128,64]
    const float* b_init = (const float*)d_in[5];   // [2,64] == concat [128]
    const float* W_mid  = (const float*)d_in[6];   // [2,128,128]
    const float* b_mid  = (const float*)d_in[7];   // [2,128]
    const float* W_last = (const float*)d_in[8];   // [128,64]
    const float* b_last = (const float*)d_in[9];   // [64]
    const float* linW   = (const float*)d_in[10];  // [256]
    const float* linb   = (const float*)d_in[11];  // [1]
    float* out = (float*)d_out;

    const int rowsG = (NN + 63) / 64;             // 782
    const int blkElem128 = (NN * 32 + 255) / 256;
    const int blkScatter128 = (EE * 32) / 256;    // 50000
    const int blkScatter64  = (EE * 16) / 256;    // 25000
    const int blkWarpRow = (NN * 32 + 255) / 256; // 6250

    // init GCNs (fused concat): s[:,0:64]=x0@W0, s[:,64:128]=x1@W1
    gemm_k<<<dim3(1, rowsG, 2), 256>>>(x_list, (long)NN * 128,
                                       W_init, (long)128 * 64, 64, 128, NN, 64);
    init_h_k<<<blkElem128, 256>>>(b_init);
    scatter128_k<<<blkScatter128, 256>>>(esrc, edst, ew);
    stats_k<<<296, 256>>>();
    fuse_first_k<<<blkWarpRow, 256>>>(b_mid);          // inp=t=x; h <- b_mid0

    gemm_k<<<dim3(2, rowsG, 1), 256>>>(nullptr, 0, W_mid, 0, 0, 128, NN, 128);
    scatter128_k<<<blkScatter128, 256>>>(esrc, edst, ew);
    stats_k<<<296, 256>>>();
    fuse_mid_k<<<blkWarpRow, 256>>>(linW, linb, b_mid + 128); // alpha; h <- b_mid1

    gemm_k<<<dim3(2, rowsG, 1), 256>>>(nullptr, 0, W_mid + (size_t)128 * 128, 0,
                                       0, 128, NN, 128);
    scatter128_k<<<blkScatter128, 256>>>(esrc, edst, ew);
    stats_k<<<296, 256>>>();
    fuse_final_k<<<blkWarpRow, 256>>>(b_last);         // t; h64 <- b_last

    gemm_k<<<dim3(1, rowsG, 1), 256>>>(nullptr, 0, W_last, 0, 0, 64, NN, 64);
    scatter64_k<<<blkScatter64, 256>>>(esrc, edst, ew);
    logsoftmax_k<<<blkWarpRow, 256>>>(out);
}

// round 3
// speedup vs baseline: 1.5859x; 1.0189x over previous
#include <cuda_runtime.h>

#define NN 50000
#define EE 400000
#define EPSBN 1e-5f

// ---------------- scratch (device globals: allocation-free) ----------------
__device__ float g_s[(size_t)NN * 128];     // GEMM output ("support")
__device__ float g_h[(size_t)NN * 128];     // aggregated gcn output
__device__ float g_inp[(size_t)NN * 128];   // residual input
__device__ float g_t[(size_t)NN * 128];     // mixed input to GEMM
__device__ float g_alpha[NN];
__device__ __align__(16) float g_stats[256]; // [0:128) sum, [128:256) sumsq

// CSR (rebuilt every launch; no caching)
__device__ int   g_deg[NN];
__device__ int   g_rowPtr[NN + 1];
__device__ int   g_cursor[NN];
__device__ int   g_blkSum[256];
__device__ int   g_blkOff[256];
__device__ int   g_csrSrc[EE];
__device__ float g_csrW[EE];

// ================= CSR build =================
__global__ __launch_bounds__(256) void zero_k()
{
    int i = blockIdx.x * blockDim.x + threadIdx.x;
    if (i < NN) g_deg[i] = 0;
    if (i < 256) g_stats[i] = 0.f;
}

__global__ __launch_bounds__(256) void hist_k(const int* __restrict__ dst)
{
    int e = blockIdx.x * blockDim.x + threadIdx.x;
    if (e < EE) atomicAdd(&g_deg[__ldg(&dst[e])], 1);
}

__global__ __launch_bounds__(256) void scan1_k()
{
    __shared__ int sh[256];
    int tid = threadIdx.x;
    int i = blockIdx.x * 256 + tid;
    int v = (i < NN) ? g_deg[i] : 0;
    sh[tid] = v; __syncthreads();
    #pragma unroll
    for (int off = 1; off < 256; off <<= 1) {
        int add = (tid >= off) ? sh[tid - off] : 0;
        __syncthreads();
        sh[tid] += add;
        __syncthreads();
    }
    if (i < NN) g_rowPtr[i + 1] = sh[tid];
    if (tid == 255) g_blkSum[blockIdx.x] = sh[255];
}

__global__ __launch_bounds__(256) void scan2_k(int nBlk)
{
    __shared__ int sh[256];
    int tid = threadIdx.x;
    sh[tid] = (tid < nBlk) ? g_blkSum[tid] : 0;
    __syncthreads();
    #pragma unroll
    for (int off = 1; off < 256; off <<= 1) {
        int add = (tid >= off) ? sh[tid - off] : 0;
        __syncthreads();
        sh[tid] += add;
        __syncthreads();
    }
    g_blkOff[tid] = (tid == 0) ? 0 : sh[tid - 1];
}

__global__ __launch_bounds__(256) void scan3_k()
{
    int i = blockIdx.x * 256 + threadIdx.x;
    if (i < NN) {
        int incl = g_rowPtr[i + 1] + g_blkOff[blockIdx.x];
        g_rowPtr[i + 1] = incl;
        g_cursor[i] = incl - g_deg[i];   // row start
    }
    if (i == 0) g_rowPtr[0] = 0;
}

__global__ __launch_bounds__(256) void fill_k(const int* __restrict__ src,
                                              const int* __restrict__ dst,
                                              const float* __restrict__ ew)
{
    int e = blockIdx.x * blockDim.x + threadIdx.x;
    if (e < EE) {
        int d = __ldg(&dst[e]);
        int pos = atomicAdd(&g_cursor[d], 1);
        g_csrSrc[pos] = __ldg(&src[e]);
        g_csrW[pos] = __ldg(&ew[e]);
    }
}

// ================= GEMM: g_s[M, ldo] = A[M,128] @ W[128,Nout] ==============
// 128 rows x (16*TN) cols per block, 256 threads, 8xTN per thread, k-chunk 32.
// A == nullptr -> read g_t. Block (0,0,0) zeroes g_stats for the next agg.
template<int TN>
__global__ __launch_bounds__(256, 2) void gemm_k(
    const float* __restrict__ A, long aBatch,
    const float* __restrict__ W, long wBatch,
    int colOffPerBatch, int ldo, int M, int Nout)
{
    constexpr int TC = 16 * TN;          // tile cols
    __shared__ float As[32][132];        // k-major, padded
    __shared__ float Ws[32][TC];
    int tid = threadIdx.x;
    if (blockIdx.x == 0 && blockIdx.y == 0 && blockIdx.z == 0 && tid < 256)
        g_stats[tid] = 0.f;
    if (A == nullptr) A = g_t;
    int b = blockIdx.z;
    A += (size_t)b * aBatch;
    W += (size_t)b * wBatch;
    int rowBase = blockIdx.y * 128;
    int colBase = blockIdx.x * TC;
    int tx = tid & 15, ty = tid >> 4;

    float acc[8][TN] = {};
    #pragma unroll
    for (int k0 = 0; k0 < 128; k0 += 32) {
        // A tile: 128 rows x 32 k -> k-major smem (transpose on store)
        #pragma unroll
        for (int j = 0; j < 4; j++) {
            int idx = tid + j * 256;
            int r = idx >> 3, kq = idx & 7;
            int gr = rowBase + r;
            float4 v = make_float4(0.f, 0.f, 0.f, 0.f);
            if (gr < M) v = *(const float4*)(A + (size_t)gr * 128 + k0 + kq * 4);
            As[kq * 4 + 0][r] = v.x; As[kq * 4 + 1][r] = v.y;
            As[kq * 4 + 2][r] = v.z; As[kq * 4 + 3][r] = v.w;
        }
        // W tile: 32 k x TC cols
        #pragma unroll
        for (int j = 0; j < TN / 2; j++) {
            int idx = tid + j * 256;
            int kk = idx / (TC / 4), c4 = idx % (TC / 4);
            float4 v = *(const float4*)(W + (size_t)(k0 + kk) * Nout + colBase + c4 * 4);
            *(float4*)&Ws[kk][c4 * 4] = v;
        }
        __syncthreads();
        #pragma unroll
        for (int k = 0; k < 32; k++) {
            float a[8], w[TN];
            *(float4*)&a[0] = *(const float4*)&As[k][ty * 8];
            *(float4*)&a[4] = *(const float4*)&As[k][ty * 8 + 4];
            *(float4*)&w[0] = *(const float4*)&Ws[k][tx * TN];
            if (TN == 8) *(float4*)&w[4] = *(const float4*)&Ws[k][tx * TN + 4];
            #pragma unroll
            for (int r = 0; r < 8; r++)
                #pragma unroll
                for (int c = 0; c < TN; c++)
                    acc[r][c] += a[r] * w[c];
        }
        __syncthreads();
    }
    int colOff = colBase + b * colOffPerBatch + tx * TN;
    #pragma unroll
    for (int r = 0; r < 8; r++) {
        int gr = rowBase + ty * 8 + r;
        if (gr < M) {
            float* p = g_s + (size_t)gr * ldo + colOff;
            *(float4*)p = *(float4*)&acc[r][0];
            if (TN == 8) *(float4*)(p + 4) = *(float4*)&acc[r][4];
        }
    }
}

// ================= aggregation: h[row] = sum_e w_e * s[src_e] ==============
// warp per row (grid-stride); lane -> 4 cols. Fused BN stats accumulation.
__global__ __launch_bounds__(256) void agg128_k()
{
    int tid = threadIdx.x;
    int lane = tid & 31;
    int wid = tid >> 5;
    int warp = (blockIdx.x * blockDim.x + tid) >> 5;
    int nWarps = (gridDim.x * blockDim.x) >> 5;

    float4 sum = make_float4(0.f, 0.f, 0.f, 0.f);
    float4 sq  = make_float4(0.f, 0.f, 0.f, 0.f);

    for (int row = warp; row < NN; row += nWarps) {
        int e = __ldg(&g_rowPtr[row]);
        int end = __ldg(&g_rowPtr[row + 1]);
        float4 acc = make_float4(0.f, 0.f, 0.f, 0.f);
        for (; e + 1 < end; e += 2) {
            int s0 = __ldg(&g_csrSrc[e]);
            int s1 = __ldg(&g_csrSrc[e + 1]);
            float w0 = __ldg(&g_csrW[e]);
            float w1 = __ldg(&g_csrW[e + 1]);
            float4 v0 = ((const float4*)(g_s + (size_t)s0 * 128))[lane];
            float4 v1 = ((const float4*)(g_s + (size_t)s1 * 128))[lane];
            acc.x += w0 * v0.x + w1 * v1.x;
            acc.y += w0 * v0.y + w1 * v1.y;
            acc.z += w0 * v0.z + w1 * v1.z;
            acc.w += w0 * v0.w + w1 * v1.w;
        }
        if (e < end) {
            int s0 = __ldg(&g_csrSrc[e]);
            float w0 = __ldg(&g_csrW[e]);
            float4 v0 = ((const float4*)(g_s + (size_t)s0 * 128))[lane];
            acc.x += w0 * v0.x; acc.y += w0 * v0.y;
            acc.z += w0 * v0.z; acc.w += w0 * v0.w;
        }
        ((float4*)(g_h + (size_t)row * 128))[lane] = acc;
        sum.x += acc.x; sum.y += acc.y; sum.z += acc.z; sum.w += acc.w;
        sq.x += acc.x * acc.x; sq.y += acc.y * acc.y;
        sq.z += acc.z * acc.z; sq.w += acc.w * acc.w;
    }

    // block reduction of stats across 8 warps, then atomics
    __shared__ float4 shs[8][32], shq[8][32];
    shs[wid][lane] = sum; shq[wid][lane] = sq;
    __syncthreads();
    #pragma unroll
    for (int off = 4; off >= 1; off >>= 1) {
        if (wid < off) {
            float4 a = shs[wid][lane], b = shs[wid + off][lane];
            a.x += b.x; a.y += b.y; a.z += b.z; a.w += b.w;
            shs[wid][lane] = a;
            float4 c = shq[wid][lane], d = shq[wid + off][lane];
            c.x += d.x; c.y += d.y; c.z += d.z; c.w += d.w;
            shq[wid][lane] = c;
        }
        __syncthreads();
    }
    if (wid == 0) {
        float4 a = shs[0][lane], c = shq[0][lane];
        int col = lane * 4;
        atomicAdd(&g_stats[col + 0], a.x);
        atomicAdd(&g_stats[col + 1], a.y);
        atomicAdd(&g_stats[col + 2], a.z);
        atomicAdd(&g_stats[col + 3], a.w);
        atomicAdd(&g_stats[128 + col + 0], c.x);
        atomicAdd(&g_stats[128 + col + 1], c.y);
        atomicAdd(&g_stats[128 + col + 2], c.z);
        atomicAdd(&g_stats[128 + col + 3], c.w);
    }
}

// final: aggregate 64-wide from g_s, add b_last, fused log_softmax -> out
__global__ __launch_bounds__(256) void agg64_softmax_k(const float* __restrict__ bLast,
                                                       float* __restrict__ out)
{
    int tid = threadIdx.x;
    int lane = tid & 31;
    int warp = (blockIdx.x * blockDim.x + tid) >> 5;
    int nWarps = (gridDim.x * blockDim.x) >> 5;
    float2 bias = ((const float2*)bLast)[lane];

    for (int row = warp; row < NN; row += nWarps) {
        int e = __ldg(&g_rowPtr[row]);
        int end = __ldg(&g_rowPtr[row + 1]);
        float2 acc = bias;
        for (; e + 1 < end; e += 2) {
            int s0 = __ldg(&g_csrSrc[e]);
            int s1 = __ldg(&g_csrSrc[e + 1]);
            float w0 = __ldg(&g_csrW[e]);
            float w1 = __ldg(&g_csrW[e + 1]);
            float2 v0 = ((const float2*)(g_s + (size_t)s0 * 64))[lane];
            float2 v1 = ((const float2*)(g_s + (size_t)s1 * 64))[lane];
            acc.x += w0 * v0.x + w1 * v1.x;
            acc.y += w0 * v0.y + w1 * v1.y;
        }
        if (e < end) {
            int s0 = __ldg(&g_csrSrc[e]);
            float w0 = __ldg(&g_csrW[e]);
            float2 v0 = ((const float2*)(g_s + (size_t)s0 * 64))[lane];
            acc.x += w0 * v0.x; acc.y += w0 * v0.y;
        }
        float m = fmaxf(acc.x, acc.y);
        #pragma unroll
        for (int o = 16; o; o >>= 1) m = fmaxf(m, __shfl_xor_sync(0xFFFFFFFFu, m, o));
        float s = expf(acc.x - m) + expf(acc.y - m);
        #pragma unroll
        for (int o = 16; o; o >>= 1) s += __shfl_xor_sync(0xFFFFFFFFu, s, o);
        float l = m + logf(s);
        ((float2*)(out + (size_t)row * 64))[lane] = make_float2(acc.x - l, acc.y - l);
    }
}

// ================= fused BN + gate kernels =================
__device__ __forceinline__ float4 bn_relu4(float4 h, int cg) {
    float4 su = ((const float4*)g_stats)[cg];
    float4 sq = ((const float4*)g_stats)[32 + cg];
    const float invN = 1.f / NN;
    float4 o;
    float mu, var;
    mu = su.x * invN; var = sq.x * invN - mu * mu;
    o.x = fmaxf((h.x - mu) * rsqrtf(var + EPSBN), 0.f);
    mu = su.y * invN; var = sq.y * invN - mu * mu;
    o.y = fmaxf((h.y - mu) * rsqrtf(var + EPSBN), 0.f);
    mu = su.z * invN; var = sq.z * invN - mu * mu;
    o.z = fmaxf((h.z - mu) * rsqrtf(var + EPSBN), 0.f);
    mu = su.w * invN; var = sq.w * invN - mu * mu;
    o.w = fmaxf((h.w - mu) * rsqrtf(var + EPSBN), 0.f);
    return o;
}

__global__ __launch_bounds__(256) void fuse_first_k()
{
    int warp = (blockIdx.x * blockDim.x + threadIdx.x) >> 5;
    if (warp >= NN) return;
    int lane = threadIdx.x & 31;
    size_t off = (size_t)warp * 32 + lane;
    float4 x = bn_relu4(((const float4*)g_h)[off], lane);
    ((float4*)g_inp)[off] = x;
    ((float4*)g_t)[off] = x;
}

__global__ __launch_bounds__(256) void fuse_mid_k(const float* __restrict__ linW,
                                                  const float* __restrict__ linb)
{
    int warp = (blockIdx.x * blockDim.x + threadIdx.x) >> 5;
    if (warp >= NN) return;
    int lane = threadIdx.x & 31;
    size_t off = (size_t)warp * 32 + lane;
    float4 x = bn_relu4(((const float4*)g_h)[off], lane);
    float4 ii = ((const float4*)g_inp)[off];
    float4 w1 = ((const float4*)linW)[lane];
    float4 w2 = ((const float4*)(linW + 128))[lane];
    float d = ii.x * w1.x + ii.y * w1.y + ii.z * w1.z + ii.w * w1.w
            + x.x * w2.x + x.y * w2.y + x.z * w2.z + x.w * w2.w;
    #pragma unroll
    for (int o = 16; o; o >>= 1) d += __shfl_xor_sync(0xFFFFFFFFu, d, o);
    float a = 1.f / (1.f + expf(-(d + linb[0])));
    float4 tv;
    tv.x = a * x.x + (1.f - a) * ii.x;
    tv.y = a * x.y + (1.f - a) * ii.y;
    tv.z = a * x.z + (1.f - a) * ii.z;
    tv.w = a * x.w + (1.f - a) * ii.w;
    ((float4*)g_t)[off] = tv;
    if (lane == 0) g_alpha[warp] = a;
}

__global__ __launch_bounds__(256) void fuse_final_k()
{
    int warp = (blockIdx.x * blockDim.x + threadIdx.x) >> 5;
    if (warp >= NN) return;
    int lane = threadIdx.x & 31;
    size_t off = (size_t)warp * 32 + lane;
    float4 x = bn_relu4(((const float4*)g_h)[off], lane);
    float4 ii = ((const float4*)g_inp)[off];
    float a = g_alpha[warp];
    float4 tv;
    tv.x = a * x.x + (1.f - a) * ii.x;
    tv.y = a * x.y + (1.f - a) * ii.y;
    tv.z = a * x.z + (1.f - a) * ii.z;
    tv.w = a * x.w + (1.f - a) * ii.w;
    ((float4*)g_t)[off] = tv;
}

// ================= launch sequence =================
extern "C" void kernel_launch(void* const* d_in, const int* in_sizes, int n_in,
                              void* d_out, int out_size)
{
    const float* x_list = (const float*)d_in[0];   // [2, N, 128]
    const int*   esrc   = (const int*)d_in[1];
    const int*   edst   = (const int*)d_in[2];
    const float* ew     = (const float*)d_in[3];
    const float* W_init = (const float*)d_in[4];   // [2,128,64]
    const float* W_mid  = (const float*)d_in[6];   // [2,128,128]
    const float* W_last = (const float*)d_in[8];   // [128,64]
    const float* b_last = (const float*)d_in[9];   // [64]
    const float* linW   = (const float*)d_in[10];  // [256]
    const float* linb   = (const float*)d_in[11];  // [1]
    float* out = (float*)d_out;

    const int nScanBlk = (NN + 255) / 256;          // 196
    const int eBlk = (EE + 255) / 256;              // 1563
    const int rowsG = (NN + 127) / 128;             // 391
    const int blkWarpRow = (NN * 32 + 255) / 256;   // 6250
    const int aggBlk = 1184;                        // 8 blocks/SM, 9472 warps

    // ---- CSR build (every launch) ----
    zero_k<<<nScanBlk, 256>>>();
    hist_k<<<eBlk, 256>>>(edst);
    scan1_k<<<nScanBlk, 256>>>();
    scan2_k<<<1, 256>>>(nScanBlk);
    scan3_k<<<nScanBlk, 256>>>();
    fill_k<<<eBlk, 256>>>(esrc, edst, ew);

    // ---- layer 1 (init GCNs, concat; bias cancels in BN) ----
    gemm_k<4><<<dim3(1, rowsG, 2), 256>>>(x_list, (long)NN * 128,
                                          W_init, (long)128 * 64, 64, 128, NN, 64);
    agg128_k<<<aggBlk, 256>>>();
    fuse_first_k<<<blkWarpRow, 256>>>();

    // ---- mid layer 0 ----
    gemm_k<8><<<dim3(1, rowsG, 1), 256>>>(nullptr, 0, W_mid, 0, 0, 128, NN, 128);
    agg128_k<<<aggBlk, 256>>>();
    fuse_mid_k<<<blkWarpRow, 256>>>(linW, linb);

    // ---- mid layer 1 ----
    gemm_k<8><<<dim3(1, rowsG, 1), 256>>>(nullptr, 0, W_mid + (size_t)128 * 128,
                                          0, 0, 128, NN, 128);
    agg128_k<<<aggBlk, 256>>>();
    fuse_final_k<<<blkWarpRow, 256>>>();

    // ---- last layer (bias + log_softmax fused into aggregation) ----
    gemm_k<4><<<dim3(1, rowsG, 1), 256>>>(nullptr, 0, W_last, 0, 0, 64, NN, 64);
    agg64_softmax_k<<<aggBlk, 256>>>(b_last, out);
}

// round 4
// speedup vs baseline: 1.7540x; 1.1060x over previous
#include <cuda_runtime.h>

#define NN 50000
#define EE 400000
#define EPSBN 1e-5f

// ---------------- scratch (device globals: allocation-free) ----------------
__device__ float g_s[(size_t)NN * 128];     // GEMM output ("support")
__device__ float g_h[(size_t)NN * 128];     // aggregated gcn output
__device__ float g_inp[(size_t)NN * 128];   // residual input
__device__ float g_t[(size_t)NN * 128];     // mixed input to GEMM
__device__ float g_alpha[NN];
__device__ __align__(16) float g_stats[256]; // [0:128) sum, [128:256) sumsq

// CSR (rebuilt every launch; no caching)
__device__ int   g_deg[NN];
__device__ int   g_rowPtr[NN + 1];
__device__ int   g_cursor[NN];
__device__ int   g_blkSum[256];
__device__ int   g_blkOff[256];
__device__ int   g_csrSrc[EE];
__device__ float g_csrW[EE];

// ================= CSR build =================
__global__ __launch_bounds__(256) void zero_k()
{
    int i = blockIdx.x * blockDim.x + threadIdx.x;
    if (i < NN) g_deg[i] = 0;
    if (i < 256) g_stats[i] = 0.f;
}

__global__ __launch_bounds__(256) void hist_k(const int* __restrict__ dst)
{
    int e = blockIdx.x * blockDim.x + threadIdx.x;
    if (e < EE) atomicAdd(&g_deg[__ldg(&dst[e])], 1);
}

__global__ __launch_bounds__(256) void scan1_k()
{
    __shared__ int sh[256];
    int tid = threadIdx.x;
    int i = blockIdx.x * 256 + tid;
    int v = (i < NN) ? g_deg[i] : 0;
    sh[tid] = v; __syncthreads();
    #pragma unroll
    for (int off = 1; off < 256; off <<= 1) {
        int add = (tid >= off) ? sh[tid - off] : 0;
        __syncthreads();
        sh[tid] += add;
        __syncthreads();
    }
    if (i < NN) g_rowPtr[i + 1] = sh[tid];
    if (tid == 255) g_blkSum[blockIdx.x] = sh[255];
}

__global__ __launch_bounds__(256) void scan2_k(int nBlk)
{
    __shared__ int sh[256];
    int tid = threadIdx.x;
    sh[tid] = (tid < nBlk) ? g_blkSum[tid] : 0;
    __syncthreads();
    #pragma unroll
    for (int off = 1; off < 256; off <<= 1) {
        int add = (tid >= off) ? sh[tid - off] : 0;
        __syncthreads();
        sh[tid] += add;
        __syncthreads();
    }
    g_blkOff[tid] = (tid == 0) ? 0 : sh[tid - 1];
}

__global__ __launch_bounds__(256) void scan3_k()
{
    int i = blockIdx.x * 256 + threadIdx.x;
    if (i < NN) {
        int incl = g_rowPtr[i + 1] + g_blkOff[blockIdx.x];
        g_rowPtr[i + 1] = incl;
        g_cursor[i] = incl - g_deg[i];   // row start
    }
    if (i == 0) g_rowPtr[0] = 0;
}

__global__ __launch_bounds__(256) void fill_k(const int* __restrict__ src,
                                              const int* __restrict__ dst,
                                              const float* __restrict__ ew)
{
    int e = blockIdx.x * blockDim.x + threadIdx.x;
    if (e < EE) {
        int d = __ldg(&dst[e]);
        int pos = atomicAdd(&g_cursor[d], 1);
        g_csrSrc[pos] = __ldg(&src[e]);
        g_csrW[pos] = __ldg(&ew[e]);
    }
}

// ================= GEMM: g_s[M, ldo] = A[M,128] @ W[128,Nout] ==============
// Tile: 64 rows x (16*TN) cols, 256 threads, 4xTN per thread, k-chunk 32.
// mode: A!=nullptr -> use A; else mode==1 -> g_inp, mode==0 -> g_t.
// Block (0,0,0) zeroes g_stats for the following aggregation.
template<int TN, int OCC>
__global__ __launch_bounds__(256, OCC) void gemm_k(
    const float* __restrict__ A, long aBatch, int mode,
    const float* __restrict__ W, long wBatch,
    int colOffPerBatch, int ldo, int M, int Nout)
{
    constexpr int TC = 16 * TN;          // tile cols
    __shared__ float As[32][68];         // k-major, padded
    __shared__ float Ws[32][TC];
    int tid = threadIdx.x;
    if (blockIdx.x == 0 && blockIdx.y == 0 && blockIdx.z == 0 && tid < 256)
        g_stats[tid] = 0.f;
    if (A == nullptr) A = mode ? g_inp : g_t;
    int b = blockIdx.z;
    A += (size_t)b * aBatch;
    W += (size_t)b * wBatch;
    int rowBase = blockIdx.y * 64;
    int colBase = blockIdx.x * TC;
    int tx = tid & 15, ty = tid >> 4;

    float acc[4][TN] = {};
    #pragma unroll
    for (int k0 = 0; k0 < 128; k0 += 32) {
        // A tile: 64 rows x 32 k -> k-major smem (transpose on store)
        #pragma unroll
        for (int j = 0; j < 2; j++) {
            int idx = tid + j * 256;
            int r = idx >> 3, kq = idx & 7;
            int gr = rowBase + r;
            float4 v = make_float4(0.f, 0.f, 0.f, 0.f);
            if (gr < M) v = *(const float4*)(A + (size_t)gr * 128 + k0 + kq * 4);
            As[kq * 4 + 0][r] = v.x; As[kq * 4 + 1][r] = v.y;
            As[kq * 4 + 2][r] = v.z; As[kq * 4 + 3][r] = v.w;
        }
        // W tile: 32 k x TC cols
        #pragma unroll
        for (int j = 0; j < TN / 2; j++) {
            int idx = tid + j * 256;
            int kk = idx / (TC / 4), c4 = idx % (TC / 4);
            float4 v = *(const float4*)(W + (size_t)(k0 + kk) * Nout + colBase + c4 * 4);
            *(float4*)&Ws[kk][c4 * 4] = v;
        }
        __syncthreads();
        #pragma unroll
        for (int k = 0; k < 32; k++) {
            float a[4], w[TN];
            *(float4*)&a[0] = *(const float4*)&As[k][ty * 4];
            *(float4*)&w[0] = *(const float4*)&Ws[k][tx * TN];
            if (TN == 8) *(float4*)&w[4] = *(const float4*)&Ws[k][tx * TN + 4];
            #pragma unroll
            for (int r = 0; r < 4; r++)
                #pragma unroll
                for (int c = 0; c < TN; c++)
                    acc[r][c] += a[r] * w[c];
        }
        __syncthreads();
    }
    int colOff = colBase + b * colOffPerBatch + tx * TN;
    #pragma unroll
    for (int r = 0; r < 4; r++) {
        int gr = rowBase + ty * 4 + r;
        if (gr < M) {
            float* p = g_s + (size_t)gr * ldo + colOff;
            *(float4*)p = *(float4*)&acc[r][0];
            if (TN == 8) *(float4*)(p + 4) = *(float4*)&acc[r][4];
        }
    }
}

// ================= aggregation: h[row] = sum_e w_e * s[src_e] ==============
// warp per row (grid-stride); lane -> 4 cols. Fused BN stats accumulation.
// 4-wide edge unroll: batch index/weight loads, then 4 independent gathers.
__global__ __launch_bounds__(256) void agg128_k()
{
    int tid = threadIdx.x;
    int lane = tid & 31;
    int wid = tid >> 5;
    int warp = (blockIdx.x * blockDim.x + tid) >> 5;
    int nWarps = (gridDim.x * blockDim.x) >> 5;

    float4 sum = make_float4(0.f, 0.f, 0.f, 0.f);
    float4 sq  = make_float4(0.f, 0.f, 0.f, 0.f);

    for (int row = warp; row < NN; row += nWarps) {
        int e = __ldg(&g_rowPtr[row]);
        int end = __ldg(&g_rowPtr[row + 1]);
        float4 acc = make_float4(0.f, 0.f, 0.f, 0.f);
        for (; e + 3 < end; e += 4) {
            int   s0 = __ldg(&g_csrSrc[e]),     s1 = __ldg(&g_csrSrc[e + 1]);
            int   s2 = __ldg(&g_csrSrc[e + 2]), s3 = __ldg(&g_csrSrc[e + 3]);
            float w0 = __ldg(&g_csrW[e]),       w1 = __ldg(&g_csrW[e + 1]);
            float w2 = __ldg(&g_csrW[e + 2]),   w3 = __ldg(&g_csrW[e + 3]);
            float4 v0 = ((const float4*)(g_s + (size_t)s0 * 128))[lane];
            float4 v1 = ((const float4*)(g_s + (size_t)s1 * 128))[lane];
            float4 v2 = ((const float4*)(g_s + (size_t)s2 * 128))[lane];
            float4 v3 = ((const float4*)(g_s + (size_t)s3 * 128))[lane];
            acc.x += w0 * v0.x + w1 * v1.x + w2 * v2.x + w3 * v3.x;
            acc.y += w0 * v0.y + w1 * v1.y + w2 * v2.y + w3 * v3.y;
            acc.z += w0 * v0.z + w1 * v1.z + w2 * v2.z + w3 * v3.z;
            acc.w += w0 * v0.w + w1 * v1.w + w2 * v2.w + w3 * v3.w;
        }
        for (; e < end; e++) {
            int s0 = __ldg(&g_csrSrc[e]);
            float w0 = __ldg(&g_csrW[e]);
            float4 v0 = ((const float4*)(g_s + (size_t)s0 * 128))[lane];
            acc.x += w0 * v0.x; acc.y += w0 * v0.y;
            acc.z += w0 * v0.z; acc.w += w0 * v0.w;
        }
        ((float4*)(g_h + (size_t)row * 128))[lane] = acc;
        sum.x += acc.x; sum.y += acc.y; sum.z += acc.z; sum.w += acc.w;
        sq.x += acc.x * acc.x; sq.y += acc.y * acc.y;
        sq.z += acc.z * acc.z; sq.w += acc.w * acc.w;
    }

    __shared__ float4 shs[8][32], shq[8][32];
    shs[wid][lane] = sum; shq[wid][lane] = sq;
    __syncthreads();
    #pragma unroll
    for (int off = 4; off >= 1; off >>= 1) {
        if (wid < off) {
            float4 a = shs[wid][lane], b = shs[wid + off][lane];
            a.x += b.x; a.y += b.y; a.z += b.z; a.w += b.w;
            shs[wid][lane] = a;
            float4 c = shq[wid][lane], d = shq[wid + off][lane];
            c.x += d.x; c.y += d.y; c.z += d.z; c.w += d.w;
            shq[wid][lane] = c;
        }
        __syncthreads();
    }
    if (wid == 0) {
        float4 a = shs[0][lane], c = shq[0][lane];
        int col = lane * 4;
        atomicAdd(&g_stats[col + 0], a.x);
        atomicAdd(&g_stats[col + 1], a.y);
        atomicAdd(&g_stats[col + 2], a.z);
        atomicAdd(&g_stats[col + 3], a.w);
        atomicAdd(&g_stats[128 + col + 0], c.x);
        atomicAdd(&g_stats[128 + col + 1], c.y);
        atomicAdd(&g_stats[128 + col + 2], c.z);
        atomicAdd(&g_stats[128 + col + 3], c.w);
    }
}

// final: aggregate 64-wide from g_s, add b_last, fused log_softmax -> out
__global__ __launch_bounds__(256) void agg64_softmax_k(const float* __restrict__ bLast,
                                                       float* __restrict__ out)
{
    int tid = threadIdx.x;
    int lane = tid & 31;
    int warp = (blockIdx.x * blockDim.x + tid) >> 5;
    int nWarps = (gridDim.x * blockDim.x) >> 5;
    float2 bias = ((const float2*)bLast)[lane];

    for (int row = warp; row < NN; row += nWarps) {
        int e = __ldg(&g_rowPtr[row]);
        int end = __ldg(&g_rowPtr[row + 1]);
        float2 acc = bias;
        for (; e + 3 < end; e += 4) {
            int   s0 = __ldg(&g_csrSrc[e]),     s1 = __ldg(&g_csrSrc[e + 1]);
            int   s2 = __ldg(&g_csrSrc[e + 2]), s3 = __ldg(&g_csrSrc[e + 3]);
            float w0 = __ldg(&g_csrW[e]),       w1 = __ldg(&g_csrW[e + 1]);
            float w2 = __ldg(&g_csrW[e + 2]),   w3 = __ldg(&g_csrW[e + 3]);
            float2 v0 = ((const float2*)(g_s + (size_t)s0 * 64))[lane];
            float2 v1 = ((const float2*)(g_s + (size_t)s1 * 64))[lane];
            float2 v2 = ((const float2*)(g_s + (size_t)s2 * 64))[lane];
            float2 v3 = ((const float2*)(g_s + (size_t)s3 * 64))[lane];
            acc.x += w0 * v0.x + w1 * v1.x + w2 * v2.x + w3 * v3.x;
            acc.y += w0 * v0.y + w1 * v1.y + w2 * v2.y + w3 * v3.y;
        }
        for (; e < end; e++) {
            int s0 = __ldg(&g_csrSrc[e]);
            float w0 = __ldg(&g_csrW[e]);
            float2 v0 = ((const float2*)(g_s + (size_t)s0 * 64))[lane];
            acc.x += w0 * v0.x; acc.y += w0 * v0.y;
        }
        float m = fmaxf(acc.x, acc.y);
        #pragma unroll
        for (int o = 16; o; o >>= 1) m = fmaxf(m, __shfl_xor_sync(0xFFFFFFFFu, m, o));
        float s = expf(acc.x - m) + expf(acc.y - m);
        #pragma unroll
        for (int o = 16; o; o >>= 1) s += __shfl_xor_sync(0xFFFFFFFFu, s, o);
        float l = m + logf(s);
        ((float2*)(out + (size_t)row * 64))[lane] = make_float2(acc.x - l, acc.y - l);
    }
}

// ================= fused BN + gate kernels =================
__device__ __forceinline__ float4 bn_relu4(float4 h, int cg) {
    float4 su = ((const float4*)g_stats)[cg];
    float4 sq = ((const float4*)g_stats)[32 + cg];
    const float invN = 1.f / NN;
    float4 o;
    float mu, var;
    mu = su.x * invN; var = sq.x * invN - mu * mu;
    o.x = fmaxf((h.x - mu) * rsqrtf(var + EPSBN), 0.f);
    mu = su.y * invN; var = sq.y * invN - mu * mu;
    o.y = fmaxf((h.y - mu) * rsqrtf(var + EPSBN), 0.f);
    mu = su.z * invN; var = sq.z * invN - mu * mu;
    o.z = fmaxf((h.z - mu) * rsqrtf(var + EPSBN), 0.f);
    mu = su.w * invN; var = sq.w * invN - mu * mu;
    o.w = fmaxf((h.w - mu) * rsqrtf(var + EPSBN), 0.f);
    return o;
}

// inp = relu(bn(h)); (first mix is identity: t == inp, GEMM reads g_inp)
__global__ __launch_bounds__(256) void fuse_first_k()
{
    int warp = (blockIdx.x * blockDim.x + threadIdx.x) >> 5;
    if (warp >= NN) return;
    int lane = threadIdx.x & 31;
    size_t off = (size_t)warp * 32 + lane;
    float4 x = bn_relu4(((const float4*)g_h)[off], lane);
    ((float4*)g_inp)[off] = x;
}

__global__ __launch_bounds__(256) void fuse_mid_k(const float* __restrict__ linW,
                                                  const float* __restrict__ linb)
{
    int warp = (blockIdx.x * blockDim.x + threadIdx.x) >> 5;
    if (warp >= NN) return;
    int lane = threadIdx.x & 31;
    size_t off = (size_t)warp * 32 + lane;
    float4 x = bn_relu4(((const float4*)g_h)[off], lane);
    float4 ii = ((const float4*)g_inp)[off];
    float4 w1 = ((const float4*)linW)[lane];
    float4 w2 = ((const float4*)(linW + 128))[lane];
    float d = ii.x * w1.x + ii.y * w1.y + ii.z * w1.z + ii.w * w1.w
            + x.x * w2.x + x.y * w2.y + x.z * w2.z + x.w * w2.w;
    #pragma unroll
    for (int o = 16; o; o >>= 1) d += __shfl_xor_sync(0xFFFFFFFFu, d, o);
    float a = 1.f / (1.f + expf(-(d + linb[0])));
    float4 tv;
    tv.x = a * x.x + (1.f - a) * ii.x;
    tv.y = a * x.y + (1.f - a) * ii.y;
    tv.z = a * x.z + (1.f - a) * ii.z;
    tv.w = a * x.w + (1.f - a) * ii.w;
    ((float4*)g_t)[off] = tv;
    if (lane == 0) g_alpha[warp] = a;
}

__global__ __launch_bounds__(256) void fuse_final_k()
{
    int warp = (blockIdx.x * blockDim.x + threadIdx.x) >> 5;
    if (warp >= NN) return;
    int lane = threadIdx.x & 31;
    size_t off = (size_t)warp * 32 + lane;
    float4 x = bn_relu4(((const float4*)g_h)[off], lane);
    float4 ii = ((const float4*)g_inp)[off];
    float a = g_alpha[warp];
    float4 tv;
    tv.x = a * x.x + (1.f - a) * ii.x;
    tv.y = a * x.y + (1.f - a) * ii.y;
    tv.z = a * x.z + (1.f - a) * ii.z;
    tv.w = a * x.w + (1.f - a) * ii.w;
    ((float4*)g_t)[off] = tv;
}

// ================= launch sequence =================
extern "C" void kernel_launch(void* const* d_in, const int* in_sizes, int n_in,
                              void* d_out, int out_size)
{
    const float* x_list = (const float*)d_in[0];   // [2, N, 128]
    const int*   esrc   = (const int*)d_in[1];
    const int*   edst   = (const int*)d_in[2];
    const float* ew     = (const float*)d_in[3];
    const float* W_init = (const float*)d_in[4];   // [2,128,64]
    const float* W_mid  = (const float*)d_in[6];   // [2,128,128]
    const float* W_last = (const float*)d_in[8];   // [128,64]
    const float* b_last = (const float*)d_in[9];   // [64]
    const float* linW   = (const float*)d_in[10];  // [256]
    const float* linb   = (const float*)d_in[11];  // [1]
    float* out = (float*)d_out;

    const int nScanBlk = (NN + 255) / 256;          // 196
    const int eBlk = (EE + 255) / 256;              // 1563
    const int rowsG = (NN + 63) / 64;               // 782
    const int blkWarpRow = (NN * 32 + 255) / 256;   // 6250
    const int aggBlk = 1184;

    // ---- CSR build (every launch) ----
    zero_k<<<nScanBlk, 256>>>();
    hist_k<<<eBlk, 256>>>(edst);
    scan1_k<<<nScanBlk, 256>>>();
    scan2_k<<<1, 256>>>(nScanBlk);
    scan3_k<<<nScanBlk, 256>>>();
    fill_k<<<eBlk, 256>>>(esrc, edst, ew);

    // ---- layer 1 (init GCNs, concat; bias cancels in BN) ----
    gemm_k<4, 6><<<dim3(1, rowsG, 2), 256>>>(x_list, (long)NN * 128, 0,
                                             W_init, (long)128 * 64, 64, 128, NN, 64);
    agg128_k<<<aggBlk, 256>>>();
    fuse_first_k<<<blkWarpRow, 256>>>();

    // ---- mid layer 0 (reads g_inp: first mix is identity) ----
    gemm_k<8, 4><<<dim3(1, rowsG, 1), 256>>>(nullptr, 0, 1,
                                             W_mid, 0, 0, 128, NN, 128);
    agg128_k<<<aggBlk, 256>>>();
    fuse_mid_k<<<blkWarpRow, 256>>>(linW, linb);

    // ---- mid layer 1 ----
    gemm_k<8, 4><<<dim3(1, rowsG, 1), 256>>>(nullptr, 0, 0,
                                             W_mid + (size_t)128 * 128, 0, 0, 128, NN, 128);
    agg128_k<<<aggBlk, 256>>>();
    fuse_final_k<<<blkWarpRow, 256>>>();

    // ---- last layer (bias + log_softmax fused into aggregation) ----
    gemm_k<4, 6><<<dim3(1, rowsG, 1), 256>>>(nullptr, 0, 0,
                                             W_last, 0, 0, 64, NN, 64);
    agg64_softmax_k<<<aggBlk, 256>>>(b_last, out);
}